// round 13
// baseline (speedup 1.0000x reference)
#include <cuda_runtime.h>

#define NFFT    1024
#define FREQ    513
#define FRAMES  2048
#define BATCH   16
#define HOP     256
#define PAD     384
#define OUTLEN  524288          // (2047*256 + 1024) - 2*384 == 2^19
#define FPB     8               // frames per block
#define FPITCH  569             // per-frame FFT pitch (float2)
#define OPITCHF 1140            // per-frame OLA pitch (floats), mult of 4
#define BPB     256             // blocks per batch (2048/8)
#define SPAN    2048            // samples advanced per block (FPB*HOP)
#define HALO    768
#define NWIN    (BATCH * (BPB + 1))    // halo windows to zero

__device__ float2 g_tw[1024];   // e^{+2*pi*i*j/1024}

// Frame-pair barrier: frames 2g,2g+1 share named barrier id 1+g (ids 1..4,
// id 0 reserved for __syncthreads), 128 threads = 4 warps.
__device__ __forceinline__ void barf(int f){
    asm volatile("bar.sync %0, 128;" :: "r"(1 + (f >> 1)) : "memory");
}

// Packed f32x2 add/sub (FADD2 path on sm_103a; bitwise identical to scalar).
__device__ __forceinline__ float2 cadd(float2 a, float2 b){
    float2 r;
    asm("add.rn.f32x2 %0, %1, %2;"
        : "=l"(reinterpret_cast<unsigned long long&>(r))
        : "l"(reinterpret_cast<const unsigned long long&>(a)),
          "l"(reinterpret_cast<const unsigned long long&>(b)));
    return r;
}
__device__ __forceinline__ float2 csub(float2 a, float2 b){
    float2 r;
    asm("sub.rn.f32x2 %0, %1, %2;"
        : "=l"(reinterpret_cast<unsigned long long&>(r))
        : "l"(reinterpret_cast<const unsigned long long&>(a)),
          "l"(reinterpret_cast<const unsigned long long&>(b)));
    return r;
}
__device__ __forceinline__ float2 cmul(float2 a, float2 b){
    return make_float2(fmaf(a.x, b.x, -a.y*b.y), fmaf(a.x, b.y, a.y*b.x));
}
__device__ __forceinline__ float2 mul_i(float2 a){return make_float2(-a.y, a.x);}

// In-place 8-point inverse DFT: y[n] = sum_m v[m] e^{+2*pi*i*m*n/8}
__device__ __forceinline__ void ifft8(float2* v){
    float2 e2a = cadd(v[0], v[4]);
    float2 e2b = csub(v[0], v[4]);
    float2 o2a = cadd(v[2], v[6]);
    float2 o2b = csub(v[2], v[6]);
    float2 E0 = cadd(e2a, o2a);
    float2 E2 = csub(e2a, o2a);
    float2 io2b = mul_i(o2b);
    float2 E1 = cadd(e2b, io2b);
    float2 E3 = csub(e2b, io2b);
    float2 p2a = cadd(v[1], v[5]);
    float2 p2b = csub(v[1], v[5]);
    float2 q2a = cadd(v[3], v[7]);
    float2 q2b = csub(v[3], v[7]);
    float2 O0 = cadd(p2a, q2a);
    float2 O2 = csub(p2a, q2a);
    float2 iq2b = mul_i(q2b);
    float2 O1 = cadd(p2b, iq2b);
    float2 O3 = csub(p2b, iq2b);
    const float C = 0.70710678118654752440f;
    float2 w1O1 = make_float2(C*(O1.x - O1.y),  C*(O1.x + O1.y));
    float2 w3O3 = make_float2(-C*(O3.x + O3.y), C*(O3.x - O3.y));
    float2 iO2  = mul_i(O2);
    v[0]=cadd(E0,O0);   v[4]=csub(E0,O0);
    v[1]=cadd(E1,w1O1); v[5]=csub(E1,w1O1);
    v[2]=cadd(E2,iO2);  v[6]=csub(E2,iO2);
    v[3]=cadd(E3,w3O3); v[7]=csub(E3,w3O3);
}

// Apply w^1..w^7 to v[1..7] via register power chain.
__device__ __forceinline__ void apply_twiddle_chain(float2* v, float2 w1){
    float2 w2 = cmul(w1, w1);
    float2 w3 = cmul(w2, w1);
    float2 w4 = cmul(w2, w2);
    float2 w5 = cmul(w3, w2);
    float2 w6 = cmul(w3, w3);
    float2 w7 = cmul(w4, w3);
    v[1] = cmul(v[1], w1);
    v[2] = cmul(v[2], w2);
    v[3] = cmul(v[3], w3);
    v[4] = cmul(v[4], w4);
    v[5] = cmul(v[5], w5);
    v[6] = cmul(v[6], w6);
    v[7] = cmul(v[7], w7);
}

// ---------------------------------------------------------------------------
// Prep kernel: one block zeroes one 768-float halo window (192 float4 stores).
// Block 0 additionally builds the twiddle table.
// ---------------------------------------------------------------------------
__global__ __launch_bounds__(192) void prep_kernel(float* __restrict__ out){
    const int r = blockIdx.x;                 // 0 .. NWIN-1
    if (r == 0) {
        for (int j = threadIdx.x; j < 1024; j += 192) {
            float s, c;
            sincosf((float)j * 6.13592315154256491887e-3f, &s, &c); // 2*pi/1024
            g_tw[j] = make_float2(c, s);
        }
    }
    const int b = r / (BPB + 1);
    const int p = r % (BPB + 1);
    const int o4start = (p * SPAN - PAD) >> 2;
    const int o4 = o4start + threadIdx.x;
    if (o4 >= 0 && o4 < OUTLEN / 4) {
        float4* dst = (float4*)(out + (size_t)b * OUTLEN);
        dst[o4] = make_float4(0.f, 0.f, 0.f, 0.f);
    }
}

// ---------------------------------------------------------------------------
// Fused kernel: Hermitian pack in the global loader, radix-8^3 on 512-pt
// complex with frame-pair named barriers, window, in-smem overlap-add.
// 512 threads = 8 frames x 64 threads; 36.5 KB smem -> 4 CTAs/SM so load
// phases of some CTAs overlap compute phases of others (DRAM overlap).
// ---------------------------------------------------------------------------
__global__ __launch_bounds__(512, 4) void istft_fused_kernel(
    const float* __restrict__ sre,
    const float* __restrict__ sim,
    const float* __restrict__ win,
    float* __restrict__ out)
{
    __shared__ float2 ctw2[8];          // e^{+2pi i a/64}
    __shared__ float2 ctw3[64];         // e^{+2pi i t/512}
    extern __shared__ float2 buf[];     // [FPB * 570] float2; reused for OLA

    const int tid = threadIdx.x;

    if (tid < 64) {
        ctw3[tid] = g_tw[2 * tid];
        if (tid < 8) ctw2[tid] = g_tw[16 * tid];
    }

    // ---- Load spectrum pair (k, 512-k) + Hermitian pack -> Z in smem -------
    const int gf0 = blockIdx.x * FPB;
    const int b   = gf0 >> 11;               // batch
    const int p   = blockIdx.x & (BPB - 1);  // block within batch
    const int fr  = gf0 & (FRAMES - 1);
    const size_t specbase = (size_t)b * FREQ * FRAMES + fr;
    {
        const int pp = tid >> 1;        // pair index 0..255
        const int q  = tid & 1;         // frame quad: frames 4q..4q+3
        if (pp == 0) {
            float4 r0   = ((const float4*)(sre + specbase))[q];
            float4 r512 = ((const float4*)(sre + specbase + (size_t)512 * FRAMES))[q];
            float4 r256 = ((const float4*)(sre + specbase + (size_t)256 * FRAMES))[q];
            float4 i256 = ((const float4*)(sim + specbase + (size_t)256 * FRAMES))[q];
            const float a0[4]  = {r0.x, r0.y, r0.z, r0.w};
            const float b0[4]  = {r512.x, r512.y, r512.z, r512.w};
            const float cr[4]  = {r256.x, r256.y, r256.z, r256.w};
            const float ci[4]  = {i256.x, i256.y, i256.z, i256.w};
#pragma unroll
            for (int j = 0; j < 4; j++) {
                float2* Zf = buf + (4 * q + j) * FPITCH;
                Zf[0]   = make_float2(a0[j] + b0[j], a0[j] - b0[j]);
                Zf[256] = make_float2(2.0f * cr[j], -2.0f * ci[j]);
            }
        } else {
            const float2 w = g_tw[pp];  // e^{+2pi i pp/1024}
            float4 ar4 = ((const float4*)(sre + specbase + (size_t)pp * FRAMES))[q];
            float4 ai4 = ((const float4*)(sim + specbase + (size_t)pp * FRAMES))[q];
            float4 br4 = ((const float4*)(sre + specbase + (size_t)(512 - pp) * FRAMES))[q];
            float4 bi4 = ((const float4*)(sim + specbase + (size_t)(512 - pp) * FRAMES))[q];
            const float ar[4] = {ar4.x, ar4.y, ar4.z, ar4.w};
            const float ai[4] = {ai4.x, ai4.y, ai4.z, ai4.w};
            const float br[4] = {br4.x, br4.y, br4.z, br4.w};
            const float bi[4] = {bi4.x, bi4.y, bi4.z, bi4.w};
#pragma unroll
            for (int j = 0; j < 4; j++) {
                const float Ur = ar[j] + br[j], Ui = ai[j] - bi[j];
                const float Vr = ar[j] - br[j], Vi = ai[j] + bi[j];
                const float Xr = w.x * Vr - w.y * Vi;
                const float Xi = w.x * Vi + w.y * Vr;
                float2* Zf = buf + (4 * q + j) * FPITCH;
                Zf[pp]       = make_float2(Ur - Xi,  Ui + Xr);
                Zf[512 - pp] = make_float2(Ur + Xi, -Ui + Xr);
            }
        }
    }
    __syncthreads();                    // FULL: loader crosses frames

    const int f = tid >> 6;             // frame within block (0..7)
    const int t = tid & 63;             // lane within frame
    float2* const Bf = buf + f * FPITCH;

    // ---- Stage 1: read Z[t+64g], ifft8, store at t + 72a -------------------
    float2 v[8];
#pragma unroll
    for (int g = 0; g < 8; g++)
        v[g] = Bf[t + 64 * g];
    barf(f);
    ifft8(v);
#pragma unroll
    for (int a = 0; a < 8; a++)
        Bf[t + 72 * a] = v[a];
    barf(f);

    // ---- Stage 2: load alpha+8be+72a, twiddle, ifft8, store a+8bb+66alpha --
    {
        const int alpha = t & 7, a = t >> 3;
#pragma unroll
        for (int be = 0; be < 8; be++)
            v[be] = Bf[alpha + 8 * be + 72 * a];
        apply_twiddle_chain(v, ctw2[a]);        // w = e^{+2pi i a/64}
        barf(f);
        ifft8(v);
#pragma unroll
        for (int bb = 0; bb < 8; bb++)
            Bf[a + 8 * bb + 66 * alpha] = v[bb];
    }
    barf(f);

    // ---- Stage 3: load t + 66alpha, twiddle, ifft8 --------------------------
    {
#pragma unroll
        for (int al = 0; al < 8; al++)
            v[al] = Bf[t + 66 * al];
        apply_twiddle_chain(v, ctw3[t]);        // w = e^{+2pi i t/512}
        ifft8(v);          // v[c] = 1024 * z[t + 64c]
    }
    barf(f);               // frame-pair's stage-3 reads done; unpack regions
                           // don't cross frame FFT regions (1140 vs 1138 pitch)

    // ---- Unpack + window into smem frame buffer (pitch OPITCHF floats) ------
    float* const frb = (float*)buf;
#pragma unroll
    for (int c = 0; c < 8; c++) {
        const int n = t + 64 * c;                   // 0..511
        float2 w2 = *(const float2*)(win + 2 * n);
        *(float2*)(frb + f * OPITCHF + 2 * n) =
            make_float2(v[c].x * w2.x * (1.0f / 1024.0f),
                        v[c].y * w2.y * (1.0f / 1024.0f));
    }
    __syncthreads();                    // FULL: OLA reads cross frames

    // ---- In-smem overlap-add over the block's 8 frames ----------------------
    const float ENV_INV = 2.0f / 3.0f;
    float* outb = out + (size_t)b * OUTLEN;
    const int nbase = p * SPAN;

    // Interior: j in [HALO, SPAN), one float4 per thread (320 tasks).
    if (tid < (SPAN - HALO) / 4) {
        const int j   = 4 * tid + HALO;             // 768..2044
        const int mb  = (j >> 8) - 3;
        const int off = j - (mb << 8);              // 768..1020, mult of 4
        const float* base = frb + mb * OPITCHF + off;
        float4 t0 = *(const float4*)(base);
        float4 t1 = *(const float4*)(base + (OPITCHF - 256));
        float4 t2 = *(const float4*)(base + 2 * (OPITCHF - 256));
        float4 t3 = *(const float4*)(base + 3 * (OPITCHF - 256));
        float4 r;
        r.x = (t0.x + t1.x + t2.x + t3.x) * ENV_INV;
        r.y = (t0.y + t1.y + t2.y + t3.y) * ENV_INV;
        r.z = (t0.z + t1.z + t2.z + t3.z) * ENV_INV;
        r.w = (t0.w + t1.w + t2.w + t3.w) * ENV_INV;
        *(float4*)(outb + nbase + j - PAD) = r;
    }

    // Edges: 1536 tasks spread over 512 threads.
#pragma unroll 1
    for (int tau = tid; tau < 2 * HALO; tau += 512) {
        const int e = (tau >= HALO);
        const int j = e ? (SPAN + tau - HALO) : tau;
        int fhi = j >> 8;         if (fhi > FPB - 1) fhi = FPB - 1;
        int flo = (j - 768) >> 8; if (flo < 0) flo = 0;
        float acc = 0.0f;
        for (int m = flo; m <= fhi; m++)
            acc += frb[m * OPITCHF + j - (m << 8)];

        const int n = nbase + j;
        const int o = n - PAD;
        if ((p == 0 && !e) || (p == BPB - 1 && e)) {
            // true batch edge: compute env from the window
            int Mhi = n >> 8;         if (Mhi > FRAMES - 1) Mhi = FRAMES - 1;
            int Mlo = (n - 768) >> 8; if (Mlo < 0) Mlo = 0;
            float env = 0.0f;
            for (int m = Mlo; m <= Mhi; m++) {
                const float w = win[n - (m << 8)];
                env += w * w;
            }
            if (o >= 0 && o < OUTLEN)
                atomicAdd(&outb[o], acc / env);
        } else {
            // interior block boundary: 4 taps globally -> env == 1.5
            atomicAdd(&outb[o], acc * ENV_INV);
        }
    }
}

// ---------------------------------------------------------------------------
extern "C" void kernel_launch(void* const* d_in, const int* in_sizes, int n_in,
                              void* d_out, int out_size)
{
    const float* sre = (const float*)d_in[0];
    const float* sim = (const float*)d_in[1];
    const float* win = (const float*)d_in[2];
    float* out = (float*)d_out;

    const int smem = FPB * 570 * (int)sizeof(float2);   // 36,480 B
    cudaFuncSetAttribute(istft_fused_kernel,
                         cudaFuncAttributeMaxDynamicSharedMemorySize, smem);

    prep_kernel<<<NWIN, 192>>>(out);
    istft_fused_kernel<<<BATCH * FRAMES / FPB, 512, smem>>>(sre, sim, win, out);
}

// round 14
// speedup vs baseline: 1.1204x; 1.1204x over previous
#include <cuda_runtime.h>

#define NFFT    1024
#define FREQ    513
#define FRAMES  2048
#define BATCH   16
#define HOP     256
#define PAD     384
#define OUTLEN  524288          // (2047*256 + 1024) - 2*384 == 2^19
#define FPB     16              // frames per block
#define FPITCH  569             // per-frame FFT pitch (float2)
#define OPITCHF 1140            // per-frame OLA pitch (floats), mult of 4
#define BPB     128             // blocks per batch (2048/16)
#define SPAN    4096            // samples advanced per block (FPB*HOP)
#define HALO    768
#define NWIN    (BATCH * (BPB + 1))    // halo windows to zero

__device__ float2 g_tw[1024];   // e^{+2*pi*i*j/1024}

// Frame-pair barrier: frames 2g,2g+1 share named barrier id 1+g (ids 1..8,
// id 0 reserved for __syncthreads), 128 threads = 4 warps.
__device__ __forceinline__ void barf(int f){
    asm volatile("bar.sync %0, 128;" :: "r"(1 + (f >> 1)) : "memory");
}

// Vector global reduction: out[0] += a.x, out[1] += a.y (one REDG.64).
__device__ __forceinline__ void red_add_v2(float* addr, float2 a){
    asm volatile("red.global.add.v2.f32 [%0], {%1, %2};"
                 :: "l"(addr), "f"(a.x), "f"(a.y) : "memory");
}

// Packed f32x2 add/sub (FADD2 path on sm_103a; bitwise identical to scalar).
__device__ __forceinline__ float2 cadd(float2 a, float2 b){
    float2 r;
    asm("add.rn.f32x2 %0, %1, %2;"
        : "=l"(reinterpret_cast<unsigned long long&>(r))
        : "l"(reinterpret_cast<const unsigned long long&>(a)),
          "l"(reinterpret_cast<const unsigned long long&>(b)));
    return r;
}
__device__ __forceinline__ float2 csub(float2 a, float2 b){
    float2 r;
    asm("sub.rn.f32x2 %0, %1, %2;"
        : "=l"(reinterpret_cast<unsigned long long&>(r))
        : "l"(reinterpret_cast<const unsigned long long&>(a)),
          "l"(reinterpret_cast<const unsigned long long&>(b)));
    return r;
}
__device__ __forceinline__ float2 cmul(float2 a, float2 b){
    return make_float2(fmaf(a.x, b.x, -a.y*b.y), fmaf(a.x, b.y, a.y*b.x));
}
__device__ __forceinline__ float2 mul_i(float2 a){return make_float2(-a.y, a.x);}

// In-place 8-point inverse DFT: y[n] = sum_m v[m] e^{+2*pi*i*m*n/8}
__device__ __forceinline__ void ifft8(float2* v){
    float2 e2a = cadd(v[0], v[4]);
    float2 e2b = csub(v[0], v[4]);
    float2 o2a = cadd(v[2], v[6]);
    float2 o2b = csub(v[2], v[6]);
    float2 E0 = cadd(e2a, o2a);
    float2 E2 = csub(e2a, o2a);
    float2 io2b = mul_i(o2b);
    float2 E1 = cadd(e2b, io2b);
    float2 E3 = csub(e2b, io2b);
    float2 p2a = cadd(v[1], v[5]);
    float2 p2b = csub(v[1], v[5]);
    float2 q2a = cadd(v[3], v[7]);
    float2 q2b = csub(v[3], v[7]);
    float2 O0 = cadd(p2a, q2a);
    float2 O2 = csub(p2a, q2a);
    float2 iq2b = mul_i(q2b);
    float2 O1 = cadd(p2b, iq2b);
    float2 O3 = csub(p2b, iq2b);
    const float C = 0.70710678118654752440f;
    float2 w1O1 = make_float2(C*(O1.x - O1.y),  C*(O1.x + O1.y));
    float2 w3O3 = make_float2(-C*(O3.x + O3.y), C*(O3.x - O3.y));
    float2 iO2  = mul_i(O2);
    v[0]=cadd(E0,O0);   v[4]=csub(E0,O0);
    v[1]=cadd(E1,w1O1); v[5]=csub(E1,w1O1);
    v[2]=cadd(E2,iO2);  v[6]=csub(E2,iO2);
    v[3]=cadd(E3,w3O3); v[7]=csub(E3,w3O3);
}

// Apply w^1..w^7 to v[1..7] via register power chain.
__device__ __forceinline__ void apply_twiddle_chain(float2* v, float2 w1){
    float2 w2 = cmul(w1, w1);
    float2 w3 = cmul(w2, w1);
    float2 w4 = cmul(w2, w2);
    float2 w5 = cmul(w3, w2);
    float2 w6 = cmul(w3, w3);
    float2 w7 = cmul(w4, w3);
    v[1] = cmul(v[1], w1);
    v[2] = cmul(v[2], w2);
    v[3] = cmul(v[3], w3);
    v[4] = cmul(v[4], w4);
    v[5] = cmul(v[5], w5);
    v[6] = cmul(v[6], w6);
    v[7] = cmul(v[7], w7);
}

// ---------------------------------------------------------------------------
// Prep kernel: one block zeroes one 768-float halo window (192 float4 stores).
// Block 0 additionally builds the twiddle table.
// ---------------------------------------------------------------------------
__global__ __launch_bounds__(192) void prep_kernel(float* __restrict__ out){
    const int r = blockIdx.x;                 // 0 .. NWIN-1
    if (r == 0) {
        for (int j = threadIdx.x; j < 1024; j += 192) {
            float s, c;
            sincosf((float)j * 6.13592315154256491887e-3f, &s, &c); // 2*pi/1024
            g_tw[j] = make_float2(c, s);
        }
    }
    const int b = r / (BPB + 1);
    const int p = r % (BPB + 1);
    const int o4start = (p * SPAN - PAD) >> 2;
    const int o4 = o4start + threadIdx.x;
    if (o4 >= 0 && o4 < OUTLEN / 4) {
        float4* dst = (float4*)(out + (size_t)b * OUTLEN);
        dst[o4] = make_float4(0.f, 0.f, 0.f, 0.f);
    }
}

// ---------------------------------------------------------------------------
// Fused kernel: Hermitian pack in the global loader, radix-8^3 on 512-pt
// complex with frame-pair named barriers (128-thread scope), window, in-smem
// overlap-add. 1024 threads = 16 frames x 64 threads. 2 full syncs only.
// ---------------------------------------------------------------------------
__global__ __launch_bounds__(1024, 2) void istft_fused_kernel(
    const float* __restrict__ sre,
    const float* __restrict__ sim,
    const float* __restrict__ win,
    float* __restrict__ out)
{
    __shared__ float2 ctw2[8];          // e^{+2pi i a/64}
    __shared__ float2 ctw3[64];         // e^{+2pi i t/512}
    extern __shared__ float2 buf[];     // [FPB * 570] float2; reused for OLA

    const int tid = threadIdx.x;

    if (tid < 64) {
        ctw3[tid] = g_tw[2 * tid];
        if (tid < 8) ctw2[tid] = g_tw[16 * tid];
    }

    // ---- Load spectrum pair (k, 512-k) + Hermitian pack -> Z in smem -------
    const int gf0 = blockIdx.x * FPB;
    const int b   = gf0 >> 11;               // batch
    const int p   = blockIdx.x & (BPB - 1);  // block within batch
    const int fr  = gf0 & (FRAMES - 1);
    const size_t specbase = (size_t)b * FREQ * FRAMES + fr;
    {
        const int pp = tid >> 2;        // pair index 0..255
        const int q  = tid & 3;         // frame quad: frames 4q..4q+3
        if (pp == 0) {
            float4 r0   = ((const float4*)(sre + specbase))[q];
            float4 r512 = ((const float4*)(sre + specbase + (size_t)512 * FRAMES))[q];
            float4 r256 = ((const float4*)(sre + specbase + (size_t)256 * FRAMES))[q];
            float4 i256 = ((const float4*)(sim + specbase + (size_t)256 * FRAMES))[q];
            const float a0[4]  = {r0.x, r0.y, r0.z, r0.w};
            const float b0[4]  = {r512.x, r512.y, r512.z, r512.w};
            const float cr[4]  = {r256.x, r256.y, r256.z, r256.w};
            const float ci[4]  = {i256.x, i256.y, i256.z, i256.w};
#pragma unroll
            for (int j = 0; j < 4; j++) {
                float2* Zf = buf + (4 * q + j) * FPITCH;
                Zf[0]   = make_float2(a0[j] + b0[j], a0[j] - b0[j]);
                Zf[256] = make_float2(2.0f * cr[j], -2.0f * ci[j]);
            }
        } else {
            const float2 w = g_tw[pp];  // e^{+2pi i pp/1024}
            float4 ar4 = ((const float4*)(sre + specbase + (size_t)pp * FRAMES))[q];
            float4 ai4 = ((const float4*)(sim + specbase + (size_t)pp * FRAMES))[q];
            float4 br4 = ((const float4*)(sre + specbase + (size_t)(512 - pp) * FRAMES))[q];
            float4 bi4 = ((const float4*)(sim + specbase + (size_t)(512 - pp) * FRAMES))[q];
            const float ar[4] = {ar4.x, ar4.y, ar4.z, ar4.w};
            const float ai[4] = {ai4.x, ai4.y, ai4.z, ai4.w};
            const float br[4] = {br4.x, br4.y, br4.z, br4.w};
            const float bi[4] = {bi4.x, bi4.y, bi4.z, bi4.w};
#pragma unroll
            for (int j = 0; j < 4; j++) {
                const float Ur = ar[j] + br[j], Ui = ai[j] - bi[j];
                const float Vr = ar[j] - br[j], Vi = ai[j] + bi[j];
                const float Xr = w.x * Vr - w.y * Vi;
                const float Xi = w.x * Vi + w.y * Vr;
                float2* Zf = buf + (4 * q + j) * FPITCH;
                Zf[pp]       = make_float2(Ur - Xi,  Ui + Xr);
                Zf[512 - pp] = make_float2(Ur + Xi, -Ui + Xr);
            }
        }
    }
    __syncthreads();                    // FULL: loader crosses frames

    const int f = tid >> 6;             // frame within block (0..15)
    const int t = tid & 63;             // lane within frame
    float2* const Bf = buf + f * FPITCH;

    // ---- Stage 1: read Z[t+64g], ifft8, store at t + 72a -------------------
    float2 v[8];
#pragma unroll
    for (int g = 0; g < 8; g++)
        v[g] = Bf[t + 64 * g];
    barf(f);
    ifft8(v);
#pragma unroll
    for (int a = 0; a < 8; a++)
        Bf[t + 72 * a] = v[a];
    barf(f);

    // ---- Stage 2: load alpha+8be+72a, twiddle, ifft8, store a+8bb+66alpha --
    {
        const int alpha = t & 7, a = t >> 3;
#pragma unroll
        for (int be = 0; be < 8; be++)
            v[be] = Bf[alpha + 8 * be + 72 * a];
        apply_twiddle_chain(v, ctw2[a]);        // w = e^{+2pi i a/64}
        barf(f);
        ifft8(v);
#pragma unroll
        for (int bb = 0; bb < 8; bb++)
            Bf[a + 8 * bb + 66 * alpha] = v[bb];
    }
    barf(f);

    // ---- Stage 3: load t + 66alpha, twiddle, ifft8 --------------------------
    {
#pragma unroll
        for (int al = 0; al < 8; al++)
            v[al] = Bf[t + 66 * al];
        apply_twiddle_chain(v, ctw3[t]);        // w = e^{+2pi i t/512}
        ifft8(v);          // v[c] = 1024 * z[t + 64c]
    }
    barf(f);               // frame-pair's stage-3 reads done; unpack regions
                           // don't cross frame FFT regions (1140 vs 1138 pitch)

    // ---- Unpack + window into smem frame buffer (pitch OPITCHF floats) ------
    float* const frb = (float*)buf;
#pragma unroll
    for (int c = 0; c < 8; c++) {
        const int n = t + 64 * c;                   // 0..511
        float2 w2 = *(const float2*)(win + 2 * n);
        *(float2*)(frb + f * OPITCHF + 2 * n) =
            make_float2(v[c].x * w2.x * (1.0f / 1024.0f),
                        v[c].y * w2.y * (1.0f / 1024.0f));
    }
    __syncthreads();                    // FULL: OLA reads cross frames

    // ---- In-smem overlap-add over the block's 16 frames ---------------------
    const float ENV_INV = 2.0f / 3.0f;
    float* outb = out + (size_t)b * OUTLEN;
    const int nbase = p * SPAN;

    // Interior: j in [HALO, SPAN), one float4 per thread (832 tasks).
    if (tid < (SPAN - HALO) / 4) {
        const int j   = 4 * tid + HALO;             // 768..4092
        const int mb  = (j >> 8) - 3;
        const int off = j - (mb << 8);              // 768..1020, mult of 4
        const float* base = frb + mb * OPITCHF + off;
        float4 t0 = *(const float4*)(base);
        float4 t1 = *(const float4*)(base + (OPITCHF - 256));
        float4 t2 = *(const float4*)(base + 2 * (OPITCHF - 256));
        float4 t3 = *(const float4*)(base + 3 * (OPITCHF - 256));
        float4 r;
        r.x = (t0.x + t1.x + t2.x + t3.x) * ENV_INV;
        r.y = (t0.y + t1.y + t2.y + t3.y) * ENV_INV;
        r.z = (t0.z + t1.z + t2.z + t3.z) * ENV_INV;
        r.w = (t0.w + t1.w + t2.w + t3.w) * ENV_INV;
        *(float4*)(outb + nbase + j - PAD) = r;
    }

    // Edges: 768 float2 tasks, one per thread (tid < 768).
    // Tap range is identical for both samples of a pair (boundaries are
    // multiples of 256; j is even).
    if (tid < 2 * HALO / 2) {
        const int e = (tid >= HALO / 2);
        const int j = e ? (SPAN + 2 * (tid - HALO / 2)) : 2 * tid;
        int fhi = j >> 8;         if (fhi > FPB - 1) fhi = FPB - 1;
        int flo = (j - 768) >> 8; if (flo < 0) flo = 0;
        float2 acc = make_float2(0.0f, 0.0f);
        for (int m = flo; m <= fhi; m++) {
            float2 tap = *(const float2*)(frb + m * OPITCHF + j - (m << 8));
            acc.x += tap.x;
            acc.y += tap.y;
        }

        const int n = nbase + j;
        const int o = n - PAD;
        if ((p == 0 && !e) || (p == BPB - 1 && e)) {
            // true batch edge: per-sample env from the window, scalar adds
#pragma unroll
            for (int s = 0; s < 2; s++) {
                const int ns = n + s, os = o + s;
                if (os < 0 || os >= OUTLEN) continue;
                int Mhi = ns >> 8;         if (Mhi > FRAMES - 1) Mhi = FRAMES - 1;
                int Mlo = (ns - 768) >> 8; if (Mlo < 0) Mlo = 0;
                float env = 0.0f;
                for (int m = Mlo; m <= Mhi; m++) {
                    const float w = win[ns - (m << 8)];
                    env += w * w;
                }
                atomicAdd(&outb[os], (s ? acc.y : acc.x) / env);
            }
        } else {
            // interior block boundary: 4 taps globally -> env == 1.5 exact
            red_add_v2(&outb[o], make_float2(acc.x * ENV_INV, acc.y * ENV_INV));
        }
    }
}

// ---------------------------------------------------------------------------
extern "C" void kernel_launch(void* const* d_in, const int* in_sizes, int n_in,
                              void* d_out, int out_size)
{
    const float* sre = (const float*)d_in[0];
    const float* sim = (const float*)d_in[1];
    const float* win = (const float*)d_in[2];
    float* out = (float*)d_out;

    const int smem = FPB * 570 * (int)sizeof(float2);   // 72,960 B
    cudaFuncSetAttribute(istft_fused_kernel,
                         cudaFuncAttributeMaxDynamicSharedMemorySize, smem);

    prep_kernel<<<NWIN, 192>>>(out);
    istft_fused_kernel<<<BATCH * FRAMES / FPB, 1024, smem>>>(sre, sim, win, out);
}